// round 13
// baseline (speedup 1.0000x reference)
#include <cuda_runtime.h>
#include <cuda_fp16.h>
#include <cstdint>

#define NN 50000
#define NE 640000
#define F  128
#define NC 16
#define BN_EPS 1e-5f

// ---------------- scratch (__device__ globals; zero-initialized at load) ----------
__device__ int    g_cnt[NN];     // re-zeroed by agg16_k at end of every call
__device__ int    g_cur[NN];
__device__ int    g_rowptr[NN + 1];
__device__ int    g_col[NE];
__device__ float  g_dinv[NN];
__device__ __half g_hh[(size_t)NN * F];      // hat-h = dinv * (seq @ W1), fp16
__device__ float  g_t[(size_t)NN * NC];      // hat-t = dinv * (x @ Wf)
__device__ float  g_wf[F * NC];              // W2 @ Wc (128 x 16)
__device__ float  g_bf[NC];                  // b2 @ Wc + bc

// ---------------- inline edge dtype sniff -------------------------------------
__device__ __forceinline__ int sniff64(const void* ei) {
    const int* p = (const int*)ei;
    return (p[1] | p[3] | p[5] | p[7]) == 0;
}

// ---------------- prep: fused classifier weights + count (4-edge ILP) ----------
__global__ void prep_k(const float* __restrict__ W2, const float* __restrict__ Wc,
                       const float* __restrict__ b2, const float* __restrict__ bc,
                       const void* ei) {
    int b = blockIdx.x, t = threadIdx.x;
    if (b < 8) {
        __shared__ float Wcs[F * NC];
        for (int i = t; i < F * NC; i += 256) Wcs[i] = Wc[i];
        __syncthreads();
        int g = b * 256 + t;              // 0..2047
        int i = g >> 4, c = g & 15;
        float acc = 0.f;
        const float* w2r = W2 + (size_t)i * F;
#pragma unroll 8
        for (int k = 0; k < F; k++) acc += w2r[k] * Wcs[k * NC + c];
        g_wf[i * NC + c] = acc;
        if (g < NC) {
            float a = bc[g];
            for (int k = 0; k < F; k++) a += b2[k] * Wcs[k * NC + g];
            g_bf[g] = a;
        }
    } else {
        int e4 = (b - 8) * 256 + t;       // 0 .. NE/4-1
        if (e4 >= NE / 4) return;
        int d0, d1, d2, d3;
        if (sniff64(ei)) {
            const longlong2* pd = (const longlong2*)((const long long*)ei + NE);
            longlong2 a = pd[2 * e4], c = pd[2 * e4 + 1];
            d0 = (int)a.x; d1 = (int)a.y; d2 = (int)c.x; d3 = (int)c.y;
        } else {
            const int4* pd = (const int4*)((const int*)ei + NE);
            int4 a = pd[e4];
            d0 = a.x; d1 = a.y; d2 = a.z; d3 = a.w;
        }
        atomicAdd(&g_cnt[d0], 1);
        atomicAdd(&g_cnt[d1], 1);
        atomicAdd(&g_cnt[d2], 1);
        atomicAdd(&g_cnt[d3], 1);
    }
}

// ---------------- single-block scan: rowptr + cursors + dinv ----------------
__global__ void scan_dinv_k() {
    __shared__ int sh[1024];
    const int CH = (NN + 1023) / 1024;  // 49
    int t = threadIdx.x;
    int beg = t * CH;
    int end = beg + CH; if (end > NN) end = NN;
    int s = 0;
    for (int i = beg; i < end; i++) s += g_cnt[i];
    sh[t] = s;
    __syncthreads();
    for (int off = 1; off < 1024; off <<= 1) {
        int v = (t >= off) ? sh[t - off] : 0;
        __syncthreads();
        sh[t] += v;
        __syncthreads();
    }
    int run = (t == 0) ? 0 : sh[t - 1];
    for (int i = beg; i < end; i++) {
        int c = g_cnt[i];
        g_rowptr[i] = run;
        g_cur[i] = run;
        g_dinv[i] = rsqrtf((float)c + 1.0f);  // +1 self loop
        run += c;
    }
    if (t == 0) g_rowptr[NN] = NE;
}

// ---------------- fill: 4 edges/thread, 4 atomics in flight ----------------
__global__ void fill_k(const void* ei) {
    int e4 = blockIdx.x * blockDim.x + threadIdx.x;   // 0 .. NE/4-1
    if (e4 >= NE / 4) return;
    int s0, s1, s2, s3, d0, d1, d2, d3;
    if (sniff64(ei)) {
        const longlong2* ps = (const longlong2*)ei;
        const longlong2* pd = (const longlong2*)((const long long*)ei + NE);
        longlong2 sa = ps[2 * e4], sb = ps[2 * e4 + 1];
        longlong2 da = pd[2 * e4], db = pd[2 * e4 + 1];
        s0 = (int)sa.x; s1 = (int)sa.y; s2 = (int)sb.x; s3 = (int)sb.y;
        d0 = (int)da.x; d1 = (int)da.y; d2 = (int)db.x; d3 = (int)db.y;
    } else {
        const int4* ps = (const int4*)ei;
        const int4* pd = (const int4*)((const int*)ei + NE);
        int4 sa = ps[e4], da = pd[e4];
        s0 = sa.x; s1 = sa.y; s2 = sa.z; s3 = sa.w;
        d0 = da.x; d1 = da.y; d2 = da.z; d3 = da.w;
    }
    int p0 = atomicAdd(&g_cur[d0], 1);
    int p1 = atomicAdd(&g_cur[d1], 1);
    int p2 = atomicAdd(&g_cur[d2], 1);
    int p3 = atomicAdd(&g_cur[d3], 1);
    g_col[p0] = s0;
    g_col[p1] = s1;
    g_col[p2] = s2;
    g_col[p3] = s3;
}

// ---------------- persistent GEMM (fma.rn.f32x2 packed fp32) ------------------
// g_hh = fp16( dinv * (X @ W1) ); grid = #SMs, W cached in smem across tiles,
// X tiles double-buffered via cp.async.
#define GEMM_TM 128
#define XST 132                               // padded row stride (floats)
#define WS_FLOATS (F * F)                     // 16384
#define XBUF_FLOATS (GEMM_TM * XST)           // 16896
#define GEMM_SMEM ((WS_FLOATS + 2 * XBUF_FLOATS) * 4)   // 200704 bytes
#define NTILES ((NN + GEMM_TM - 1) / GEMM_TM) // 391

__device__ __forceinline__ uint32_t smem_u32(const void* p) {
    uint32_t a;
    asm("{ .reg .u64 t; cvta.to.shared.u64 t, %1; cvt.u32.u64 %0, t; }" : "=r"(a) : "l"(p));
    return a;
}
__device__ __forceinline__ void cp16(uint32_t d, const void* s, int sz) {
    asm volatile("cp.async.cg.shared.global [%0], [%1], 16, %2;"
                 :: "r"(d), "l"(s), "r"(sz));
}
#define CP_COMMIT() asm volatile("cp.async.commit_group;" ::: "memory")
#define CP_WAIT1()  asm volatile("cp.async.wait_group 1;" ::: "memory")

// packed 2xfp32 FMA (Blackwell family PTX; full fp32 precision per lane)
__device__ __forceinline__ void ffma2(unsigned long long& d, unsigned long long a,
                                      unsigned long long b) {
    asm("fma.rn.f32x2 %0, %1, %2, %0;" : "+l"(d) : "l"(a), "l"(b));
}
__device__ __forceinline__ unsigned long long packxx(float x) {
    unsigned long long r;
    asm("mov.b64 %0, {%1, %1};" : "=l"(r) : "r"(__float_as_uint(x)));
    return r;
}
__device__ __forceinline__ float2 unpack2(unsigned long long v) {
    unsigned int lo, hi;
    asm("mov.b64 {%0, %1}, %2;" : "=r"(lo), "=r"(hi) : "l"(v));
    return make_float2(__uint_as_float(lo), __uint_as_float(hi));
}

__device__ __forceinline__ void stage_x_async(const float* __restrict__ X, int tile,
                                              uint32_t xs, int tid) {
    int base = tile * GEMM_TM;
#pragma unroll
    for (int p = 0; p < GEMM_TM * 32 / 512; p++) {        // 8 per thread
        int i = p * 512 + tid;
        int r = i >> 5, c4 = i & 31;
        int gr = base + r;
        const float4* src = (const float4*)X + ((gr < NN) ? ((size_t)gr * 32 + c4) : 0);
        cp16(xs + (uint32_t)(r * XST + c4 * 4) * 4, src, (gr < NN) ? 16 : 0);
    }
}

__global__ __launch_bounds__(512, 1) void gemm_k(const float* __restrict__ X,
                                                 const float* __restrict__ W) {
    extern __shared__ float sm[];
    float* Ws = sm;
    uint32_t ws_u = smem_u32(sm);
    uint32_t xb_u[2] = { ws_u + WS_FLOATS * 4, ws_u + (WS_FLOATS + XBUF_FLOATS) * 4 };
    float* Xb[2] = { sm + WS_FLOATS, sm + WS_FLOATS + XBUF_FLOATS };

    int tid = threadIdx.x;

    // stage W (once) + first X tile, one async group
    const float4* W4 = (const float4*)W;
#pragma unroll
    for (int p = 0; p < 4096 / 512; p++) {                 // 8 per thread
        int i = p * 512 + tid;
        cp16(ws_u + (uint32_t)i * 16, W4 + i, 16);
    }
    stage_x_async(X, blockIdx.x, xb_u[0], tid);
    CP_COMMIT();

    int colg = tid & 15;
    int rowg = tid >> 4;
    int c0 = colg * 4;
    int r0 = rowg * 4;
    int cur = 0;

    for (int t = blockIdx.x; t < NTILES; t += gridDim.x) {
        int nxt = t + gridDim.x;
        if (nxt < NTILES) stage_x_async(X, nxt, xb_u[cur ^ 1], tid);
        CP_COMMIT();
        CP_WAIT1();            // oldest group (current tile + W on first iter) done
        __syncthreads();

        const float* Xs = Xb[cur];
        // packed accumulators: acc[r][p] = cols {c0+2p, c0+2p+1} (p<2) and
        // {c0+64+2(p-2), ...} (p>=2)
        unsigned long long acc[4][4];
#pragma unroll
        for (int i = 0; i < 4; i++)
#pragma unroll
            for (int p = 0; p < 4; p++) acc[i][p] = 0ULL;

#pragma unroll 4
        for (int k4 = 0; k4 < 32; k4++) {
            float4 xv[4];
#pragma unroll
            for (int i = 0; i < 4; i++)
                xv[i] = *(const float4*)&Xs[(r0 + i) * XST + k4 * 4];
#pragma unroll
            for (int kk = 0; kk < 4; kk++) {
                int k = k4 * 4 + kk;
                ulonglong2 wa = *(const ulonglong2*)&Ws[k * F + c0];       // 4 cols
                ulonglong2 wb = *(const ulonglong2*)&Ws[k * F + c0 + 64];  // 4 cols
#pragma unroll
                for (int i = 0; i < 4; i++) {
                    float xr = (kk == 0) ? xv[i].x : (kk == 1) ? xv[i].y
                             : (kk == 2) ? xv[i].z : xv[i].w;
                    unsigned long long xx = packxx(xr);
                    ffma2(acc[i][0], xx, wa.x);
                    ffma2(acc[i][1], xx, wa.y);
                    ffma2(acc[i][2], xx, wb.x);
                    ffma2(acc[i][3], xx, wb.y);
                }
            }
        }

        int base = t * GEMM_TM;
        uint2* H2 = (uint2*)g_hh;
#pragma unroll
        for (int i = 0; i < 4; i++) {
            int gr = base + r0 + i;
            if (gr < NN) {
                float dv = g_dinv[gr];
                float2 p0 = unpack2(acc[i][0]);
                float2 p1 = unpack2(acc[i][1]);
                float2 p2 = unpack2(acc[i][2]);
                float2 p3 = unpack2(acc[i][3]);
                __half2 a0 = __floats2half2_rn(p0.x * dv, p0.y * dv);
                __half2 a1 = __floats2half2_rn(p1.x * dv, p1.y * dv);
                __half2 b0 = __floats2half2_rn(p2.x * dv, p2.y * dv);
                __half2 b1 = __floats2half2_rn(p3.x * dv, p3.y * dv);
                uint2 ua, ub;
                ua.x = *(uint32_t*)&a0; ua.y = *(uint32_t*)&a1;
                ub.x = *(uint32_t*)&b0; ub.y = *(uint32_t*)&b1;
                H2[(size_t)gr * 32 + colg] = ua;
                H2[(size_t)gr * 32 + 16 + colg] = ub;
            }
        }
        __syncthreads();       // everyone done reading Xs[cur] before it is refilled
        cur ^= 1;
    }
}

// ---------------- fused L1-agg + BN + ReLU + (row @ Wf) * dinv -> g_t ---------
// warp per node; 8-edge unroll (8 gathers in flight) -> 4 fp32 accumulators.
__global__ void agg128f_k(float* __restrict__ T,
                          const float* __restrict__ bias, const float* __restrict__ gamma,
                          const float* __restrict__ beta, const float* __restrict__ mean,
                          const float* __restrict__ var) {
    __shared__ float Wfs[F * NC];          // 8 KB
    __shared__ float os[8][F];             // per-warp row stash, 4 KB
    int tid = threadIdx.x;
    for (int i = tid; i < F * NC; i += 256) Wfs[i] = g_wf[i];
    __syncthreads();

    int gw = (blockIdx.x * blockDim.x + tid) >> 5;
    int lane = tid & 31;
    int wrp = tid >> 5;
    if (gw >= NN) return;
    int n = gw;
    const uint2* H2 = (const uint2*)g_hh;

    uint2 u = H2[(size_t)n * 32 + lane];                       // self loop
    float2 f0 = __half22float2(*reinterpret_cast<__half2*>(&u.x));
    float2 f1 = __half22float2(*reinterpret_cast<__half2*>(&u.y));
    float4 ac0 = make_float4(f0.x, f0.y, f1.x, f1.y);
    float4 ac1 = make_float4(0.f, 0.f, 0.f, 0.f);
    float4 ac2 = make_float4(0.f, 0.f, 0.f, 0.f);
    float4 ac3 = make_float4(0.f, 0.f, 0.f, 0.f);

    int jb = g_rowptr[n], je = g_rowptr[n + 1];
    int j = jb;
    for (; j + 8 <= je; j += 8) {
        uint2 v[8];
#pragma unroll
        for (int e = 0; e < 8; e++)
            v[e] = H2[(size_t)g_col[j + e] * 32 + lane];
#pragma unroll
        for (int e = 0; e < 8; e++) {
            float2 a = __half22float2(*reinterpret_cast<__half2*>(&v[e].x));
            float2 b = __half22float2(*reinterpret_cast<__half2*>(&v[e].y));
            float4* ac = (e & 3) == 0 ? &ac0 : (e & 3) == 1 ? &ac1 : (e & 3) == 2 ? &ac2 : &ac3;
            ac->x += a.x; ac->y += a.y; ac->z += b.x; ac->w += b.y;
        }
    }
    for (; j + 4 <= je; j += 4) {
        uint2 v0 = H2[(size_t)g_col[j]     * 32 + lane];
        uint2 v1 = H2[(size_t)g_col[j + 1] * 32 + lane];
        uint2 v2 = H2[(size_t)g_col[j + 2] * 32 + lane];
        uint2 v3 = H2[(size_t)g_col[j + 3] * 32 + lane];
        float2 a0 = __half22float2(*reinterpret_cast<__half2*>(&v0.x));
        float2 b0 = __half22float2(*reinterpret_cast<__half2*>(&v0.y));
        float2 a1 = __half22float2(*reinterpret_cast<__half2*>(&v1.x));
        float2 b1 = __half22float2(*reinterpret_cast<__half2*>(&v1.y));
        float2 a2 = __half22float2(*reinterpret_cast<__half2*>(&v2.x));
        float2 b2 = __half22float2(*reinterpret_cast<__half2*>(&v2.y));
        float2 a3 = __half22float2(*reinterpret_cast<__half2*>(&v3.x));
        float2 b3 = __half22float2(*reinterpret_cast<__half2*>(&v3.y));
        ac0.x += a0.x; ac0.y += a0.y; ac0.z += b0.x; ac0.w += b0.y;
        ac1.x += a1.x; ac1.y += a1.y; ac1.z += b1.x; ac1.w += b1.y;
        ac2.x += a2.x; ac2.y += a2.y; ac2.z += b2.x; ac2.w += b2.y;
        ac3.x += a3.x; ac3.y += a3.y; ac3.z += b3.x; ac3.w += b3.y;
    }
    for (; j < je; j++) {
        uint2 v = H2[(size_t)g_col[j] * 32 + lane];
        float2 a = __half22float2(*reinterpret_cast<__half2*>(&v.x));
        float2 b = __half22float2(*reinterpret_cast<__half2*>(&v.y));
        ac0.x += a.x; ac0.y += a.y; ac0.z += b.x; ac0.w += b.y;
    }
    float4 acc;
    acc.x = (ac0.x + ac1.x) + (ac2.x + ac3.x);
    acc.y = (ac0.y + ac1.y) + (ac2.y + ac3.y);
    acc.z = (ac0.z + ac1.z) + (ac2.z + ac3.z);
    acc.w = (ac0.w + ac1.w) + (ac2.w + ac3.w);

    float dn = g_dinv[n];
    float4 b = ((const float4*)bias)[lane];
    float4 gm = ((const float4*)gamma)[lane];
    float4 bt = ((const float4*)beta)[lane];
    float4 mn = ((const float4*)mean)[lane];
    float4 vr = ((const float4*)var)[lane];
    float4 o;
    o.x = fmaxf(0.f, (dn * acc.x + b.x - mn.x) * rsqrtf(vr.x + BN_EPS) * gm.x + bt.x);
    o.y = fmaxf(0.f, (dn * acc.y + b.y - mn.y) * rsqrtf(vr.y + BN_EPS) * gm.y + bt.y);
    o.z = fmaxf(0.f, (dn * acc.z + b.z - mn.z) * rsqrtf(vr.z + BN_EPS) * gm.z + bt.z);
    o.w = fmaxf(0.f, (dn * acc.w + b.w - mn.w) * rsqrtf(vr.w + BN_EPS) * gm.w + bt.w);

    *(float4*)&os[wrp][lane * 4] = o;
    __syncwarp();
    if (lane < 16) {
        float pc = 0.f;
#pragma unroll 8
        for (int k4 = 0; k4 < 32; k4++) {
            float4 ov = *(const float4*)&os[wrp][k4 * 4];
            int kb = k4 * 4;
            pc += ov.x * Wfs[(kb + 0) * NC + lane] + ov.y * Wfs[(kb + 1) * NC + lane] +
                  ov.z * Wfs[(kb + 2) * NC + lane] + ov.w * Wfs[(kb + 3) * NC + lane];
        }
        T[(size_t)n * NC + lane] = pc * dn;
    }
}

// ---------------- aggregation L2: 4 threads/node; writes output; re-zeros cnt --
__global__ void agg16_k(const float* __restrict__ t, float* __restrict__ out) {
    int idx = blockIdx.x * blockDim.x + threadIdx.x;
    int n = idx >> 2;
    int q = idx & 3;
    if (n >= NN) return;
    if (q == 0) g_cnt[n] = 0;   // reset for next call (counts already consumed)
    const float4* t4 = (const float4*)t;

    float4 ac0 = t4[(size_t)n * 4 + q];  // self loop
    float4 ac1 = make_float4(0.f, 0.f, 0.f, 0.f);
    float4 ac2 = make_float4(0.f, 0.f, 0.f, 0.f);
    float4 ac3 = make_float4(0.f, 0.f, 0.f, 0.f);
    int jb = g_rowptr[n], je = g_rowptr[n + 1];
    int j = jb;
    for (; j + 4 <= je; j += 4) {
        float4 v0 = t4[(size_t)g_col[j]     * 4 + q];
        float4 v1 = t4[(size_t)g_col[j + 1] * 4 + q];
        float4 v2 = t4[(size_t)g_col[j + 2] * 4 + q];
        float4 v3 = t4[(size_t)g_col[j + 3] * 4 + q];
        ac0.x += v0.x; ac0.y += v0.y; ac0.z += v0.z; ac0.w += v0.w;
        ac1.x += v1.x; ac1.y += v1.y; ac1.z += v1.z; ac1.w += v1.w;
        ac2.x += v2.x; ac2.y += v2.y; ac2.z += v2.z; ac2.w += v2.w;
        ac3.x += v3.x; ac3.y += v3.y; ac3.z += v3.z; ac3.w += v3.w;
    }
    for (; j < je; j++) {
        float4 v = t4[(size_t)g_col[j] * 4 + q];
        ac0.x += v.x; ac0.y += v.y; ac0.z += v.z; ac0.w += v.w;
    }
    float4 acc;
    acc.x = (ac0.x + ac1.x) + (ac2.x + ac3.x);
    acc.y = (ac0.y + ac1.y) + (ac2.y + ac3.y);
    acc.z = (ac0.z + ac1.z) + (ac2.z + ac3.z);
    acc.w = (ac0.w + ac1.w) + (ac2.w + ac3.w);

    float dn = g_dinv[n];
    float4 b = ((const float4*)g_bf)[q];
    acc.x = dn * acc.x + b.x; acc.y = dn * acc.y + b.y;
    acc.z = dn * acc.z + b.z; acc.w = dn * acc.w + b.w;
    ((float4*)out)[(size_t)n * 4 + q] = acc;
}

// ---------------- launch (6 kernels) ----------------
extern "C" void kernel_launch(void* const* d_in, const int* in_sizes, int n_in,
                              void* d_out, int out_size) {
    const float* seq   = (const float*)d_in[0];
    const void*  ei    = d_in[1];
    const float* W1    = (const float*)d_in[2];
    const float* b1    = (const float*)d_in[3];
    const float* gamma = (const float*)d_in[4];
    const float* beta  = (const float*)d_in[5];
    const float* rmean = (const float*)d_in[6];
    const float* rvar  = (const float*)d_in[7];
    const float* W2    = (const float*)d_in[8];
    const float* b2    = (const float*)d_in[9];
    const float* Wc    = (const float*)d_in[10];
    const float* bc    = (const float*)d_in[11];
    float* out = (float*)d_out;

    float* gt = nullptr;
    cudaGetSymbolAddress((void**)&gt, g_t);

    int nsm = 148;
    cudaDeviceGetAttribute(&nsm, cudaDevAttrMultiProcessorCount, 0);
    if (nsm <= 0 || nsm > NTILES) nsm = 148;

    cudaFuncSetAttribute(gemm_k, cudaFuncAttributeMaxDynamicSharedMemorySize, GEMM_SMEM);

    // prep: Wf fuse + count (g_cnt zeroed by prior call / static init)
    prep_k<<<8 + NE / 4 / 256, 256>>>(W2, Wc, b2, bc, ei);
    scan_dinv_k<<<1, 1024>>>();
    fill_k<<<NE / 4 / 256, 256>>>(ei);

    // layer 1: hh = fp16(dinv * (seq @ W1)); persistent, f32x2 packed FMA
    gemm_k<<<nsm, 512, GEMM_SMEM>>>(seq, W1);
    agg128f_k<<<(NN * 32 + 255) / 256, 256>>>(gt, b1, gamma, beta, rmean, rvar);

    // layer 2 (pre-projected): out = dinv * agg(t-hat) + bf ; also re-zero cnt
    agg16_k<<<(NN * 4 + 255) / 256, 256>>>(gt, out);
}

// round 14
// speedup vs baseline: 1.0049x; 1.0049x over previous
#include <cuda_runtime.h>
#include <cuda_fp16.h>
#include <cstdint>

#define NN 50000
#define NE 640000
#define F  128
#define NC 16
#define BN_EPS 1e-5f

// ---------------- scratch (__device__ globals; zero-initialized at load) ----------
__device__ int    g_cnt[NN];     // re-zeroed by agg16_k at end of every call
__device__ int    g_cur[NN];
__device__ int    g_rowptr[NN + 1];
__device__ int    g_col[NE];
__device__ float  g_dinv[NN];
__device__ __half g_hh[(size_t)NN * F];      // hat-h = dinv * (seq @ W1), fp16
__device__ float  g_t[(size_t)NN * NC];      // hat-t = dinv * (x @ Wf)
__device__ float  g_wf[F * NC];              // W2 @ Wc (128 x 16)
__device__ float  g_bf[NC];                  // b2 @ Wc + bc

// ---------------- inline edge dtype sniff -------------------------------------
__device__ __forceinline__ int sniff64(const void* ei) {
    const int* p = (const int*)ei;
    return (p[1] | p[3] | p[5] | p[7]) == 0;
}

// ---------------- prep: fused classifier weights + count (4-edge ILP) ----------
__global__ void prep_k(const float* __restrict__ W2, const float* __restrict__ Wc,
                       const float* __restrict__ b2, const float* __restrict__ bc,
                       const void* ei) {
    int b = blockIdx.x, t = threadIdx.x;
    if (b < 8) {
        __shared__ float Wcs[F * NC];
        for (int i = t; i < F * NC; i += 256) Wcs[i] = Wc[i];
        __syncthreads();
        int g = b * 256 + t;              // 0..2047
        int i = g >> 4, c = g & 15;
        float acc = 0.f;
        const float* w2r = W2 + (size_t)i * F;
#pragma unroll 8
        for (int k = 0; k < F; k++) acc += w2r[k] * Wcs[k * NC + c];
        g_wf[i * NC + c] = acc;
        if (g < NC) {
            float a = bc[g];
            for (int k = 0; k < F; k++) a += b2[k] * Wcs[k * NC + g];
            g_bf[g] = a;
        }
    } else {
        int e4 = (b - 8) * 256 + t;       // 0 .. NE/4-1
        if (e4 >= NE / 4) return;
        int d0, d1, d2, d3;
        if (sniff64(ei)) {
            const longlong2* pd = (const longlong2*)((const long long*)ei + NE);
            longlong2 a = pd[2 * e4], c = pd[2 * e4 + 1];
            d0 = (int)a.x; d1 = (int)a.y; d2 = (int)c.x; d3 = (int)c.y;
        } else {
            const int4* pd = (const int4*)((const int*)ei + NE);
            int4 a = pd[e4];
            d0 = a.x; d1 = a.y; d2 = a.z; d3 = a.w;
        }
        atomicAdd(&g_cnt[d0], 1);
        atomicAdd(&g_cnt[d1], 1);
        atomicAdd(&g_cnt[d2], 1);
        atomicAdd(&g_cnt[d3], 1);
    }
}

// ---------------- single-block scan (8-way unrolled loads for MLP) -------------
__global__ void scan_dinv_k() {
    __shared__ int sh[1024];
    const int CH = (NN + 1023) / 1024;  // 49
    int t = threadIdx.x;
    int beg = t * CH;
    int end = beg + CH; if (end > NN) end = NN;

    int s = 0;
    int i = beg;
    for (; i + 8 <= end; i += 8) {
        int c0 = g_cnt[i + 0], c1 = g_cnt[i + 1], c2 = g_cnt[i + 2], c3 = g_cnt[i + 3];
        int c4 = g_cnt[i + 4], c5 = g_cnt[i + 5], c6 = g_cnt[i + 6], c7 = g_cnt[i + 7];
        s += ((c0 + c1) + (c2 + c3)) + ((c4 + c5) + (c6 + c7));
    }
    for (; i < end; i++) s += g_cnt[i];
    sh[t] = s;
    __syncthreads();
    for (int off = 1; off < 1024; off <<= 1) {
        int v = (t >= off) ? sh[t - off] : 0;
        __syncthreads();
        sh[t] += v;
        __syncthreads();
    }
    int run = (t == 0) ? 0 : sh[t - 1];
    i = beg;
    for (; i + 8 <= end; i += 8) {
        int c[8];
#pragma unroll
        for (int e = 0; e < 8; e++) c[e] = g_cnt[i + e];
#pragma unroll
        for (int e = 0; e < 8; e++) {
            g_rowptr[i + e] = run;
            g_cur[i + e] = run;
            g_dinv[i + e] = rsqrtf((float)c[e] + 1.0f);
            run += c[e];
        }
    }
    for (; i < end; i++) {
        int c = g_cnt[i];
        g_rowptr[i] = run;
        g_cur[i] = run;
        g_dinv[i] = rsqrtf((float)c + 1.0f);
        run += c;
    }
    if (t == 0) g_rowptr[NN] = NE;
}

// ---------------- CSR fill slice (called from inside gemm; overlaps cp.async) --
__device__ __forceinline__ void fill_slice(const void* ei, int start, int stride) {
    int f64 = sniff64(ei);
    for (int e4 = start; e4 < NE / 4; e4 += stride) {
        int s0, s1, s2, s3, d0, d1, d2, d3;
        if (f64) {
            const longlong2* ps = (const longlong2*)ei;
            const longlong2* pd = (const longlong2*)((const long long*)ei + NE);
            longlong2 sa = ps[2 * e4], sb = ps[2 * e4 + 1];
            longlong2 da = pd[2 * e4], db = pd[2 * e4 + 1];
            s0 = (int)sa.x; s1 = (int)sa.y; s2 = (int)sb.x; s3 = (int)sb.y;
            d0 = (int)da.x; d1 = (int)da.y; d2 = (int)db.x; d3 = (int)db.y;
        } else {
            const int4* ps = (const int4*)ei;
            const int4* pd = (const int4*)((const int*)ei + NE);
            int4 sa = ps[e4], da = pd[e4];
            s0 = sa.x; s1 = sa.y; s2 = sa.z; s3 = sa.w;
            d0 = da.x; d1 = da.y; d2 = da.z; d3 = da.w;
        }
        int p0 = atomicAdd(&g_cur[d0], 1);
        int p1 = atomicAdd(&g_cur[d1], 1);
        int p2 = atomicAdd(&g_cur[d2], 1);
        int p3 = atomicAdd(&g_cur[d3], 1);
        g_col[p0] = s0;
        g_col[p1] = s1;
        g_col[p2] = s2;
        g_col[p3] = s3;
    }
}

// ---------------- persistent GEMM (f32x2) + embedded CSR fill -----------------
// g_hh = fp16( dinv * (X @ W1) ); grid = #SMs, W cached in smem across tiles,
// X double-buffered via cp.async. CSR fill runs while the first async group
// is in flight (fill is L2-latency work; gemm is FMA/LDS work — they overlap).
#define GEMM_TM 128
#define XST 132                               // padded row stride (floats)
#define WS_FLOATS (F * F)                     // 16384
#define XBUF_FLOATS (GEMM_TM * XST)           // 16896
#define GEMM_SMEM ((WS_FLOATS + 2 * XBUF_FLOATS) * 4)   // 200704 bytes
#define NTILES ((NN + GEMM_TM - 1) / GEMM_TM) // 391

__device__ __forceinline__ uint32_t smem_u32(const void* p) {
    uint32_t a;
    asm("{ .reg .u64 t; cvta.to.shared.u64 t, %1; cvt.u32.u64 %0, t; }" : "=r"(a) : "l"(p));
    return a;
}
__device__ __forceinline__ void cp16(uint32_t d, const void* s, int sz) {
    asm volatile("cp.async.cg.shared.global [%0], [%1], 16, %2;"
                 :: "r"(d), "l"(s), "r"(sz));
}
#define CP_COMMIT() asm volatile("cp.async.commit_group;" ::: "memory")
#define CP_WAIT1()  asm volatile("cp.async.wait_group 1;" ::: "memory")

__device__ __forceinline__ void ffma2(unsigned long long& d, unsigned long long a,
                                      unsigned long long b) {
    asm("fma.rn.f32x2 %0, %1, %2, %0;" : "+l"(d) : "l"(a), "l"(b));
}
__device__ __forceinline__ unsigned long long packxx(float x) {
    unsigned long long r;
    asm("mov.b64 %0, {%1, %1};" : "=l"(r) : "r"(__float_as_uint(x)));
    return r;
}
__device__ __forceinline__ float2 unpack2(unsigned long long v) {
    unsigned int lo, hi;
    asm("mov.b64 {%0, %1}, %2;" : "=r"(lo), "=r"(hi) : "l"(v));
    return make_float2(__uint_as_float(lo), __uint_as_float(hi));
}

__device__ __forceinline__ void stage_x_async(const float* __restrict__ X, int tile,
                                              uint32_t xs, int tid) {
    int base = tile * GEMM_TM;
#pragma unroll
    for (int p = 0; p < GEMM_TM * 32 / 512; p++) {        // 8 per thread
        int i = p * 512 + tid;
        int r = i >> 5, c4 = i & 31;
        int gr = base + r;
        const float4* src = (const float4*)X + ((gr < NN) ? ((size_t)gr * 32 + c4) : 0);
        cp16(xs + (uint32_t)(r * XST + c4 * 4) * 4, src, (gr < NN) ? 16 : 0);
    }
}

__global__ __launch_bounds__(512, 1) void gemm_k(const float* __restrict__ X,
                                                 const float* __restrict__ W,
                                                 const void* ei) {
    extern __shared__ float sm[];
    float* Ws = sm;
    uint32_t ws_u = smem_u32(sm);
    uint32_t xb_u[2] = { ws_u + WS_FLOATS * 4, ws_u + (WS_FLOATS + XBUF_FLOATS) * 4 };
    float* Xb[2] = { sm + WS_FLOATS, sm + WS_FLOATS + XBUF_FLOATS };

    int tid = threadIdx.x;

    // stage W (once) + first X tile, one async group
    const float4* W4 = (const float4*)W;
#pragma unroll
    for (int p = 0; p < 4096 / 512; p++) {                 // 8 per thread
        int i = p * 512 + tid;
        cp16(ws_u + (uint32_t)i * 16, W4 + i, 16);
    }
    stage_x_async(X, blockIdx.x, xb_u[0], tid);
    CP_COMMIT();

    // CSR fill while the async group streams in (atomic-latency work overlaps)
    fill_slice(ei, blockIdx.x * 512 + tid, gridDim.x * 512);

    int colg = tid & 15;
    int rowg = tid >> 4;
    int c0 = colg * 4;
    int r0 = rowg * 4;
    int cur = 0;

    for (int t = blockIdx.x; t < NTILES; t += gridDim.x) {
        int nxt = t + gridDim.x;
        if (nxt < NTILES) stage_x_async(X, nxt, xb_u[cur ^ 1], tid);
        CP_COMMIT();
        CP_WAIT1();            // oldest group (current tile + W on first iter) done
        __syncthreads();

        const float* Xs = Xb[cur];
        unsigned long long acc[4][4];
#pragma unroll
        for (int i = 0; i < 4; i++)
#pragma unroll
            for (int p = 0; p < 4; p++) acc[i][p] = 0ULL;

#pragma unroll 4
        for (int k4 = 0; k4 < 32; k4++) {
            float4 xv[4];
#pragma unroll
            for (int i = 0; i < 4; i++)
                xv[i] = *(const float4*)&Xs[(r0 + i) * XST + k4 * 4];
#pragma unroll
            for (int kk = 0; kk < 4; kk++) {
                int k = k4 * 4 + kk;
                ulonglong2 wa = *(const ulonglong2*)&Ws[k * F + c0];       // 4 cols
                ulonglong2 wb = *(const ulonglong2*)&Ws[k * F + c0 + 64];  // 4 cols
#pragma unroll
                for (int i = 0; i < 4; i++) {
                    float xr = (kk == 0) ? xv[i].x : (kk == 1) ? xv[i].y
                             : (kk == 2) ? xv[i].z : xv[i].w;
                    unsigned long long xx = packxx(xr);
                    ffma2(acc[i][0], xx, wa.x);
                    ffma2(acc[i][1], xx, wa.y);
                    ffma2(acc[i][2], xx, wb.x);
                    ffma2(acc[i][3], xx, wb.y);
                }
            }
        }

        int base = t * GEMM_TM;
        uint2* H2 = (uint2*)g_hh;
#pragma unroll
        for (int i = 0; i < 4; i++) {
            int gr = base + r0 + i;
            if (gr < NN) {
                float dv = g_dinv[gr];
                float2 p0 = unpack2(acc[i][0]);
                float2 p1 = unpack2(acc[i][1]);
                float2 p2 = unpack2(acc[i][2]);
                float2 p3 = unpack2(acc[i][3]);
                __half2 a0 = __floats2half2_rn(p0.x * dv, p0.y * dv);
                __half2 a1 = __floats2half2_rn(p1.x * dv, p1.y * dv);
                __half2 b0 = __floats2half2_rn(p2.x * dv, p2.y * dv);
                __half2 b1 = __floats2half2_rn(p3.x * dv, p3.y * dv);
                uint2 ua, ub;
                ua.x = *(uint32_t*)&a0; ua.y = *(uint32_t*)&a1;
                ub.x = *(uint32_t*)&b0; ub.y = *(uint32_t*)&b1;
                H2[(size_t)gr * 32 + colg] = ua;
                H2[(size_t)gr * 32 + 16 + colg] = ub;
            }
        }
        __syncthreads();       // everyone done reading Xs[cur] before it is refilled
        cur ^= 1;
    }
}

// ---------------- fused L1-agg + BN + ReLU + (row @ Wf) * dinv -> g_t ---------
__global__ void agg128f_k(float* __restrict__ T,
                          const float* __restrict__ bias, const float* __restrict__ gamma,
                          const float* __restrict__ beta, const float* __restrict__ mean,
                          const float* __restrict__ var) {
    __shared__ float Wfs[F * NC];          // 8 KB
    __shared__ float os[8][F];             // per-warp row stash, 4 KB
    int tid = threadIdx.x;
    for (int i = tid; i < F * NC; i += 256) Wfs[i] = g_wf[i];
    __syncthreads();

    int gw = (blockIdx.x * blockDim.x + tid) >> 5;
    int lane = tid & 31;
    int wrp = tid >> 5;
    if (gw >= NN) return;
    int n = gw;
    const uint2* H2 = (const uint2*)g_hh;

    uint2 u = H2[(size_t)n * 32 + lane];                       // self loop
    float2 f0 = __half22float2(*reinterpret_cast<__half2*>(&u.x));
    float2 f1 = __half22float2(*reinterpret_cast<__half2*>(&u.y));
    float4 ac0 = make_float4(f0.x, f0.y, f1.x, f1.y);
    float4 ac1 = make_float4(0.f, 0.f, 0.f, 0.f);
    float4 ac2 = make_float4(0.f, 0.f, 0.f, 0.f);
    float4 ac3 = make_float4(0.f, 0.f, 0.f, 0.f);

    int jb = g_rowptr[n], je = g_rowptr[n + 1];
    int j = jb;
    for (; j + 8 <= je; j += 8) {
        uint2 v[8];
#pragma unroll
        for (int e = 0; e < 8; e++)
            v[e] = H2[(size_t)g_col[j + e] * 32 + lane];
#pragma unroll
        for (int e = 0; e < 8; e++) {
            float2 a = __half22float2(*reinterpret_cast<__half2*>(&v[e].x));
            float2 b = __half22float2(*reinterpret_cast<__half2*>(&v[e].y));
            float4* ac = (e & 3) == 0 ? &ac0 : (e & 3) == 1 ? &ac1 : (e & 3) == 2 ? &ac2 : &ac3;
            ac->x += a.x; ac->y += a.y; ac->z += b.x; ac->w += b.y;
        }
    }
    for (; j + 4 <= je; j += 4) {
        uint2 v0 = H2[(size_t)g_col[j]     * 32 + lane];
        uint2 v1 = H2[(size_t)g_col[j + 1] * 32 + lane];
        uint2 v2 = H2[(size_t)g_col[j + 2] * 32 + lane];
        uint2 v3 = H2[(size_t)g_col[j + 3] * 32 + lane];
        float2 a0 = __half22float2(*reinterpret_cast<__half2*>(&v0.x));
        float2 b0 = __half22float2(*reinterpret_cast<__half2*>(&v0.y));
        float2 a1 = __half22float2(*reinterpret_cast<__half2*>(&v1.x));
        float2 b1 = __half22float2(*reinterpret_cast<__half2*>(&v1.y));
        float2 a2 = __half22float2(*reinterpret_cast<__half2*>(&v2.x));
        float2 b2 = __half22float2(*reinterpret_cast<__half2*>(&v2.y));
        float2 a3 = __half22float2(*reinterpret_cast<__half2*>(&v3.x));
        float2 b3 = __half22float2(*reinterpret_cast<__half2*>(&v3.y));
        ac0.x += a0.x; ac0.y += a0.y; ac0.z += b0.x; ac0.w += b0.y;
        ac1.x += a1.x; ac1.y += a1.y; ac1.z += b1.x; ac1.w += b1.y;
        ac2.x += a2.x; ac2.y += a2.y; ac2.z += b2.x; ac2.w += b2.y;
        ac3.x += a3.x; ac3.y += a3.y; ac3.z += b3.x; ac3.w += b3.y;
    }
    for (; j < je; j++) {
        uint2 v = H2[(size_t)g_col[j] * 32 + lane];
        float2 a = __half22float2(*reinterpret_cast<__half2*>(&v.x));
        float2 b = __half22float2(*reinterpret_cast<__half2*>(&v.y));
        ac0.x += a.x; ac0.y += a.y; ac0.z += b.x; ac0.w += b.y;
    }
    float4 acc;
    acc.x = (ac0.x + ac1.x) + (ac2.x + ac3.x);
    acc.y = (ac0.y + ac1.y) + (ac2.y + ac3.y);
    acc.z = (ac0.z + ac1.z) + (ac2.z + ac3.z);
    acc.w = (ac0.w + ac1.w) + (ac2.w + ac3.w);

    float dn = g_dinv[n];
    float4 b = ((const float4*)bias)[lane];
    float4 gm = ((const float4*)gamma)[lane];
    float4 bt = ((const float4*)beta)[lane];
    float4 mn = ((const float4*)mean)[lane];
    float4 vr = ((const float4*)var)[lane];
    float4 o;
    o.x = fmaxf(0.f, (dn * acc.x + b.x - mn.x) * rsqrtf(vr.x + BN_EPS) * gm.x + bt.x);
    o.y = fmaxf(0.f, (dn * acc.y + b.y - mn.y) * rsqrtf(vr.y + BN_EPS) * gm.y + bt.y);
    o.z = fmaxf(0.f, (dn * acc.z + b.z - mn.z) * rsqrtf(vr.z + BN_EPS) * gm.z + bt.z);
    o.w = fmaxf(0.f, (dn * acc.w + b.w - mn.w) * rsqrtf(vr.w + BN_EPS) * gm.w + bt.w);

    *(float4*)&os[wrp][lane * 4] = o;
    __syncwarp();
    if (lane < 16) {
        float pc = 0.f;
#pragma unroll 8
        for (int k4 = 0; k4 < 32; k4++) {
            float4 ov = *(const float4*)&os[wrp][k4 * 4];
            int kb = k4 * 4;
            pc += ov.x * Wfs[(kb + 0) * NC + lane] + ov.y * Wfs[(kb + 1) * NC + lane] +
                  ov.z * Wfs[(kb + 2) * NC + lane] + ov.w * Wfs[(kb + 3) * NC + lane];
        }
        T[(size_t)n * NC + lane] = pc * dn;
    }
}

// ---------------- aggregation L2: 4 threads/node; writes output; re-zeros cnt --
__global__ void agg16_k(const float* __restrict__ t, float* __restrict__ out) {
    int idx = blockIdx.x * blockDim.x + threadIdx.x;
    int n = idx >> 2;
    int q = idx & 3;
    if (n >= NN) return;
    if (q == 0) g_cnt[n] = 0;   // reset for next call (counts already consumed)
    const float4* t4 = (const float4*)t;

    float4 ac0 = t4[(size_t)n * 4 + q];  // self loop
    float4 ac1 = make_float4(0.f, 0.f, 0.f, 0.f);
    float4 ac2 = make_float4(0.f, 0.f, 0.f, 0.f);
    float4 ac3 = make_float4(0.f, 0.f, 0.f, 0.f);
    int jb = g_rowptr[n], je = g_rowptr[n + 1];
    int j = jb;
    for (; j + 4 <= je; j += 4) {
        float4 v0 = t4[(size_t)g_col[j]     * 4 + q];
        float4 v1 = t4[(size_t)g_col[j + 1] * 4 + q];
        float4 v2 = t4[(size_t)g_col[j + 2] * 4 + q];
        float4 v3 = t4[(size_t)g_col[j + 3] * 4 + q];
        ac0.x += v0.x; ac0.y += v0.y; ac0.z += v0.z; ac0.w += v0.w;
        ac1.x += v1.x; ac1.y += v1.y; ac1.z += v1.z; ac1.w += v1.w;
        ac2.x += v2.x; ac2.y += v2.y; ac2.z += v2.z; ac2.w += v2.w;
        ac3.x += v3.x; ac3.y += v3.y; ac3.z += v3.z; ac3.w += v3.w;
    }
    for (; j < je; j++) {
        float4 v = t4[(size_t)g_col[j] * 4 + q];
        ac0.x += v.x; ac0.y += v.y; ac0.z += v.z; ac0.w += v.w;
    }
    float4 acc;
    acc.x = (ac0.x + ac1.x) + (ac2.x + ac3.x);
    acc.y = (ac0.y + ac1.y) + (ac2.y + ac3.y);
    acc.z = (ac0.z + ac1.z) + (ac2.z + ac3.z);
    acc.w = (ac0.w + ac1.w) + (ac2.w + ac3.w);

    float dn = g_dinv[n];
    float4 b = ((const float4*)g_bf)[q];
    acc.x = dn * acc.x + b.x; acc.y = dn * acc.y + b.y;
    acc.z = dn * acc.z + b.z; acc.w = dn * acc.w + b.w;
    ((float4*)out)[(size_t)n * 4 + q] = acc;
}

// ---------------- launch (5 kernels) ----------------
extern "C" void kernel_launch(void* const* d_in, const int* in_sizes, int n_in,
                              void* d_out, int out_size) {
    const float* seq   = (const float*)d_in[0];
    const void*  ei    = d_in[1];
    const float* W1    = (const float*)d_in[2];
    const float* b1    = (const float*)d_in[3];
    const float* gamma = (const float*)d_in[4];
    const float* beta  = (const float*)d_in[5];
    const float* rmean = (const float*)d_in[6];
    const float* rvar  = (const float*)d_in[7];
    const float* W2    = (const float*)d_in[8];
    const float* b2    = (const float*)d_in[9];
    const float* Wc    = (const float*)d_in[10];
    const float* bc    = (const float*)d_in[11];
    float* out = (float*)d_out;

    float* gt = nullptr;
    cudaGetSymbolAddress((void**)&gt, g_t);

    int nsm = 148;
    cudaDeviceGetAttribute(&nsm, cudaDevAttrMultiProcessorCount, 0);
    if (nsm <= 0 || nsm > NTILES) nsm = 148;

    cudaFuncSetAttribute(gemm_k, cudaFuncAttributeMaxDynamicSharedMemorySize, GEMM_SMEM);

    // prep: Wf fuse + degree count (g_cnt zeroed by prior call / static init)
    prep_k<<<8 + NE / 4 / 256, 256>>>(W2, Wc, b2, bc, ei);
    scan_dinv_k<<<1, 1024>>>();

    // layer 1 GEMM + embedded CSR fill (fill overlaps async staging/compute)
    gemm_k<<<nsm, 512, GEMM_SMEM>>>(seq, W1, ei);
    agg128f_k<<<(NN * 32 + 255) / 256, 256>>>(gt, b1, gamma, beta, rmean, rvar);

    // layer 2 (pre-projected): out = dinv * agg(t-hat) + bf ; also re-zero cnt
    agg16_k<<<(NN * 4 + 255) / 256, 256>>>(gt, out);
}

// round 15
// speedup vs baseline: 1.1140x; 1.1086x over previous
#include <cuda_runtime.h>
#include <cuda_fp16.h>
#include <cstdint>

#define NN 50000
#define NE 640000
#define F  128
#define NC 16
#define BN_EPS 1e-5f

// ---------------- scratch (__device__ globals; zero-initialized at load) ----------
__device__ int    g_cnt[NN];     // re-zeroed by agg16_k at end of every call
__device__ int    g_cur[NN];
__device__ int    g_rowptr[NN + 1];
__device__ int    g_col[NE];
__device__ float  g_dinv[NN];
__device__ __half g_hh[(size_t)NN * F];      // hat-h = dinv * (seq @ W1), fp16
__device__ float  g_t[(size_t)NN * NC];      // hat-t = dinv * (x @ Wf)
__device__ float  g_wf[F * NC];              // W2 @ Wc (128 x 16)
__device__ float  g_bf[NC];                  // b2 @ Wc + bc

// ---------------- inline edge dtype sniff -------------------------------------
__device__ __forceinline__ int sniff64(const void* ei) {
    const int* p = (const int*)ei;
    return (p[1] | p[3] | p[5] | p[7]) == 0;
}

// ---------------- f32x2 helpers ------------------------------------------------
__device__ __forceinline__ void ffma2(unsigned long long& d, unsigned long long a,
                                      unsigned long long b) {
    asm("fma.rn.f32x2 %0, %1, %2, %0;" : "+l"(d) : "l"(a), "l"(b));
}
__device__ __forceinline__ unsigned long long packxx(float x) {
    unsigned long long r;
    asm("mov.b64 %0, {%1, %1};" : "=l"(r) : "r"(__float_as_uint(x)));
    return r;
}
__device__ __forceinline__ float2 unpack2(unsigned long long v) {
    unsigned int lo, hi;
    asm("mov.b64 {%0, %1}, %2;" : "=r"(lo), "=r"(hi) : "l"(v));
    return make_float2(__uint_as_float(lo), __uint_as_float(hi));
}

// ---------------- prep: fused classifier weights + count (4-edge ILP) ----------
__global__ void prep_k(const float* __restrict__ W2, const float* __restrict__ Wc,
                       const float* __restrict__ b2, const float* __restrict__ bc,
                       const void* ei) {
    int b = blockIdx.x, t = threadIdx.x;
    if (b < 8) {
        __shared__ float Wcs[F * NC];
        for (int i = t; i < F * NC; i += 256) Wcs[i] = Wc[i];
        __syncthreads();
        int g = b * 256 + t;              // 0..2047
        int i = g >> 4, c = g & 15;
        float acc = 0.f;
        const float* w2r = W2 + (size_t)i * F;
#pragma unroll 8
        for (int k = 0; k < F; k++) acc += w2r[k] * Wcs[k * NC + c];
        g_wf[i * NC + c] = acc;
        if (g < NC) {
            float a = bc[g];
            for (int k = 0; k < F; k++) a += b2[k] * Wcs[k * NC + g];
            g_bf[g] = a;
        }
    } else {
        int e4 = (b - 8) * 256 + t;       // 0 .. NE/4-1
        if (e4 >= NE / 4) return;
        int d0, d1, d2, d3;
        if (sniff64(ei)) {
            const longlong2* pd = (const longlong2*)((const long long*)ei + NE);
            longlong2 a = pd[2 * e4], c = pd[2 * e4 + 1];
            d0 = (int)a.x; d1 = (int)a.y; d2 = (int)c.x; d3 = (int)c.y;
        } else {
            const int4* pd = (const int4*)((const int*)ei + NE);
            int4 a = pd[e4];
            d0 = a.x; d1 = a.y; d2 = a.z; d3 = a.w;
        }
        atomicAdd(&g_cnt[d0], 1);
        atomicAdd(&g_cnt[d1], 1);
        atomicAdd(&g_cnt[d2], 1);
        atomicAdd(&g_cnt[d3], 1);
    }
}

// ---------------- single-block scan (8-way unrolled loads for MLP) -------------
__global__ void scan_dinv_k() {
    __shared__ int sh[1024];
    const int CH = (NN + 1023) / 1024;  // 49
    int t = threadIdx.x;
    int beg = t * CH;
    int end = beg + CH; if (end > NN) end = NN;

    int s = 0;
    int i = beg;
    for (; i + 8 <= end; i += 8) {
        int c0 = g_cnt[i + 0], c1 = g_cnt[i + 1], c2 = g_cnt[i + 2], c3 = g_cnt[i + 3];
        int c4 = g_cnt[i + 4], c5 = g_cnt[i + 5], c6 = g_cnt[i + 6], c7 = g_cnt[i + 7];
        s += ((c0 + c1) + (c2 + c3)) + ((c4 + c5) + (c6 + c7));
    }
    for (; i < end; i++) s += g_cnt[i];
    sh[t] = s;
    __syncthreads();
    for (int off = 1; off < 1024; off <<= 1) {
        int v = (t >= off) ? sh[t - off] : 0;
        __syncthreads();
        sh[t] += v;
        __syncthreads();
    }
    int run = (t == 0) ? 0 : sh[t - 1];
    i = beg;
    for (; i + 8 <= end; i += 8) {
        int c[8];
#pragma unroll
        for (int e = 0; e < 8; e++) c[e] = g_cnt[i + e];
#pragma unroll
        for (int e = 0; e < 8; e++) {
            g_rowptr[i + e] = run;
            g_cur[i + e] = run;
            g_dinv[i + e] = rsqrtf((float)c[e] + 1.0f);
            run += c[e];
        }
    }
    for (; i < end; i++) {
        int c = g_cnt[i];
        g_rowptr[i] = run;
        g_cur[i] = run;
        g_dinv[i] = rsqrtf((float)c + 1.0f);
        run += c;
    }
    if (t == 0) g_rowptr[NN] = NE;
}

// ---------------- CSR fill slice (called from inside gemm; overlaps cp.async) --
__device__ __forceinline__ void fill_slice(const void* ei, int start, int stride) {
    int f64 = sniff64(ei);
    for (int e4 = start; e4 < NE / 4; e4 += stride) {
        int s0, s1, s2, s3, d0, d1, d2, d3;
        if (f64) {
            const longlong2* ps = (const longlong2*)ei;
            const longlong2* pd = (const longlong2*)((const long long*)ei + NE);
            longlong2 sa = ps[2 * e4], sb = ps[2 * e4 + 1];
            longlong2 da = pd[2 * e4], db = pd[2 * e4 + 1];
            s0 = (int)sa.x; s1 = (int)sa.y; s2 = (int)sb.x; s3 = (int)sb.y;
            d0 = (int)da.x; d1 = (int)da.y; d2 = (int)db.x; d3 = (int)db.y;
        } else {
            const int4* ps = (const int4*)ei;
            const int4* pd = (const int4*)((const int*)ei + NE);
            int4 sa = ps[e4], da = pd[e4];
            s0 = sa.x; s1 = sa.y; s2 = sa.z; s3 = sa.w;
            d0 = da.x; d1 = da.y; d2 = da.z; d3 = da.w;
        }
        int p0 = atomicAdd(&g_cur[d0], 1);
        int p1 = atomicAdd(&g_cur[d1], 1);
        int p2 = atomicAdd(&g_cur[d2], 1);
        int p3 = atomicAdd(&g_cur[d3], 1);
        g_col[p0] = s0;
        g_col[p1] = s1;
        g_col[p2] = s2;
        g_col[p3] = s3;
    }
}

// ---------------- persistent GEMM (f32x2) + embedded CSR fill -----------------
#define GEMM_TM 128
#define XST 132                               // padded row stride (floats)
#define WS_FLOATS (F * F)                     // 16384
#define XBUF_FLOATS (GEMM_TM * XST)           // 16896
#define GEMM_SMEM ((WS_FLOATS + 2 * XBUF_FLOATS) * 4)   // 200704 bytes
#define NTILES ((NN + GEMM_TM - 1) / GEMM_TM) // 391

__device__ __forceinline__ uint32_t smem_u32(const void* p) {
    uint32_t a;
    asm("{ .reg .u64 t; cvta.to.shared.u64 t, %1; cvt.u32.u64 %0, t; }" : "=r"(a) : "l"(p));
    return a;
}
__device__ __forceinline__ void cp16(uint32_t d, const void* s, int sz) {
    asm volatile("cp.async.cg.shared.global [%0], [%1], 16, %2;"
                 :: "r"(d), "l"(s), "r"(sz));
}
#define CP_COMMIT() asm volatile("cp.async.commit_group;" ::: "memory")
#define CP_WAIT1()  asm volatile("cp.async.wait_group 1;" ::: "memory")

__device__ __forceinline__ void stage_x_async(const float* __restrict__ X, int tile,
                                              uint32_t xs, int tid) {
    int base = tile * GEMM_TM;
#pragma unroll
    for (int p = 0; p < GEMM_TM * 32 / 512; p++) {        // 8 per thread
        int i = p * 512 + tid;
        int r = i >> 5, c4 = i & 31;
        int gr = base + r;
        const float4* src = (const float4*)X + ((gr < NN) ? ((size_t)gr * 32 + c4) : 0);
        cp16(xs + (uint32_t)(r * XST + c4 * 4) * 4, src, (gr < NN) ? 16 : 0);
    }
}

__global__ __launch_bounds__(512, 1) void gemm_k(const float* __restrict__ X,
                                                 const float* __restrict__ W,
                                                 const void* ei) {
    extern __shared__ float sm[];
    float* Ws = sm;
    uint32_t ws_u = smem_u32(sm);
    uint32_t xb_u[2] = { ws_u + WS_FLOATS * 4, ws_u + (WS_FLOATS + XBUF_FLOATS) * 4 };
    float* Xb[2] = { sm + WS_FLOATS, sm + WS_FLOATS + XBUF_FLOATS };

    int tid = threadIdx.x;

    const float4* W4 = (const float4*)W;
#pragma unroll
    for (int p = 0; p < 4096 / 512; p++) {
        int i = p * 512 + tid;
        cp16(ws_u + (uint32_t)i * 16, W4 + i, 16);
    }
    stage_x_async(X, blockIdx.x, xb_u[0], tid);
    CP_COMMIT();

    // CSR fill while the async group streams in
    fill_slice(ei, blockIdx.x * 512 + tid, gridDim.x * 512);

    int colg = tid & 15;
    int rowg = tid >> 4;
    int c0 = colg * 4;
    int r0 = rowg * 4;
    int cur = 0;

    for (int t = blockIdx.x; t < NTILES; t += gridDim.x) {
        int nxt = t + gridDim.x;
        if (nxt < NTILES) stage_x_async(X, nxt, xb_u[cur ^ 1], tid);
        CP_COMMIT();
        CP_WAIT1();
        __syncthreads();

        const float* Xs = Xb[cur];
        unsigned long long acc[4][4];
#pragma unroll
        for (int i = 0; i < 4; i++)
#pragma unroll
            for (int p = 0; p < 4; p++) acc[i][p] = 0ULL;

#pragma unroll 4
        for (int k4 = 0; k4 < 32; k4++) {
            float4 xv[4];
#pragma unroll
            for (int i = 0; i < 4; i++)
                xv[i] = *(const float4*)&Xs[(r0 + i) * XST + k4 * 4];
#pragma unroll
            for (int kk = 0; kk < 4; kk++) {
                int k = k4 * 4 + kk;
                ulonglong2 wa = *(const ulonglong2*)&Ws[k * F + c0];
                ulonglong2 wb = *(const ulonglong2*)&Ws[k * F + c0 + 64];
#pragma unroll
                for (int i = 0; i < 4; i++) {
                    float xr = (kk == 0) ? xv[i].x : (kk == 1) ? xv[i].y
                             : (kk == 2) ? xv[i].z : xv[i].w;
                    unsigned long long xx = packxx(xr);
                    ffma2(acc[i][0], xx, wa.x);
                    ffma2(acc[i][1], xx, wa.y);
                    ffma2(acc[i][2], xx, wb.x);
                    ffma2(acc[i][3], xx, wb.y);
                }
            }
        }

        int base = t * GEMM_TM;
        uint2* H2 = (uint2*)g_hh;
#pragma unroll
        for (int i = 0; i < 4; i++) {
            int gr = base + r0 + i;
            if (gr < NN) {
                float dv = g_dinv[gr];
                float2 p0 = unpack2(acc[i][0]);
                float2 p1 = unpack2(acc[i][1]);
                float2 p2 = unpack2(acc[i][2]);
                float2 p3 = unpack2(acc[i][3]);
                __half2 a0 = __floats2half2_rn(p0.x * dv, p0.y * dv);
                __half2 a1 = __floats2half2_rn(p1.x * dv, p1.y * dv);
                __half2 b0 = __floats2half2_rn(p2.x * dv, p2.y * dv);
                __half2 b1 = __floats2half2_rn(p3.x * dv, p3.y * dv);
                uint2 ua, ub;
                ua.x = *(uint32_t*)&a0; ua.y = *(uint32_t*)&a1;
                ub.x = *(uint32_t*)&b0; ub.y = *(uint32_t*)&b1;
                H2[(size_t)gr * 32 + colg] = ua;
                H2[(size_t)gr * 32 + 16 + colg] = ub;
            }
        }
        __syncthreads();
        cur ^= 1;
    }
}

// ---------------- fused L1-agg + BN + ReLU + packed (row @ Wf) * dinv ---------
// warp per node. Projection: all 32 lanes, f32x2 FMA over paired Wf columns.
#define OST 136   // os row stride in floats (544 B: 16B-aligned rows)

__global__ void agg128f_k(float* __restrict__ T,
                          const float* __restrict__ bias, const float* __restrict__ gamma,
                          const float* __restrict__ beta, const float* __restrict__ mean,
                          const float* __restrict__ var) {
    __shared__ float2 Wfp[64 * NC];        // paired Wf: Wfp[k2*16+c] = (Wf[2k2][c], Wf[2k2+1][c])
    __shared__ float os[8][OST];           // per-warp row stash
    int tid = threadIdx.x;
    for (int i = tid; i < 64 * NC; i += 256) {
        int k2 = i >> 4, c = i & 15;
        Wfp[i] = make_float2(g_wf[(2 * k2) * NC + c], g_wf[(2 * k2 + 1) * NC + c]);
    }
    __syncthreads();

    int gw = (blockIdx.x * blockDim.x + tid) >> 5;
    int lane = tid & 31;
    int wrp = tid >> 5;
    if (gw >= NN) return;
    int n = gw;
    const uint2* H2 = (const uint2*)g_hh;

    uint2 u = H2[(size_t)n * 32 + lane];                       // self loop
    float2 f0 = __half22float2(*reinterpret_cast<__half2*>(&u.x));
    float2 f1 = __half22float2(*reinterpret_cast<__half2*>(&u.y));
    float4 ac0 = make_float4(f0.x, f0.y, f1.x, f1.y);
    float4 ac1 = make_float4(0.f, 0.f, 0.f, 0.f);
    float4 ac2 = make_float4(0.f, 0.f, 0.f, 0.f);
    float4 ac3 = make_float4(0.f, 0.f, 0.f, 0.f);

    int jb = g_rowptr[n], je = g_rowptr[n + 1];
    int j = jb;
    for (; j + 8 <= je; j += 8) {
        uint2 v[8];
#pragma unroll
        for (int e = 0; e < 8; e++)
            v[e] = H2[(size_t)g_col[j + e] * 32 + lane];
#pragma unroll
        for (int e = 0; e < 8; e++) {
            float2 a = __half22float2(*reinterpret_cast<__half2*>(&v[e].x));
            float2 b = __half22float2(*reinterpret_cast<__half2*>(&v[e].y));
            float4* ac = (e & 3) == 0 ? &ac0 : (e & 3) == 1 ? &ac1 : (e & 3) == 2 ? &ac2 : &ac3;
            ac->x += a.x; ac->y += a.y; ac->z += b.x; ac->w += b.y;
        }
    }
    for (; j + 4 <= je; j += 4) {
        uint2 v0 = H2[(size_t)g_col[j]     * 32 + lane];
        uint2 v1 = H2[(size_t)g_col[j + 1] * 32 + lane];
        uint2 v2 = H2[(size_t)g_col[j + 2] * 32 + lane];
        uint2 v3 = H2[(size_t)g_col[j + 3] * 32 + lane];
        float2 a0 = __half22float2(*reinterpret_cast<__half2*>(&v0.x));
        float2 b0 = __half22float2(*reinterpret_cast<__half2*>(&v0.y));
        float2 a1 = __half22float2(*reinterpret_cast<__half2*>(&v1.x));
        float2 b1 = __half22float2(*reinterpret_cast<__half2*>(&v1.y));
        float2 a2 = __half22float2(*reinterpret_cast<__half2*>(&v2.x));
        float2 b2 = __half22float2(*reinterpret_cast<__half2*>(&v2.y));
        float2 a3 = __half22float2(*reinterpret_cast<__half2*>(&v3.x));
        float2 b3 = __half22float2(*reinterpret_cast<__half2*>(&v3.y));
        ac0.x += a0.x; ac0.y += a0.y; ac0.z += b0.x; ac0.w += b0.y;
        ac1.x += a1.x; ac1.y += a1.y; ac1.z += b1.x; ac1.w += b1.y;
        ac2.x += a2.x; ac2.y += a2.y; ac2.z += b2.x; ac2.w += b2.y;
        ac3.x += a3.x; ac3.y += a3.y; ac3.z += b3.x; ac3.w += b3.y;
    }
    for (; j < je; j++) {
        uint2 v = H2[(size_t)g_col[j] * 32 + lane];
        float2 a = __half22float2(*reinterpret_cast<__half2*>(&v.x));
        float2 b = __half22float2(*reinterpret_cast<__half2*>(&v.y));
        ac0.x += a.x; ac0.y += a.y; ac0.z += b.x; ac0.w += b.y;
    }
    float4 acc;
    acc.x = (ac0.x + ac1.x) + (ac2.x + ac3.x);
    acc.y = (ac0.y + ac1.y) + (ac2.y + ac3.y);
    acc.z = (ac0.z + ac1.z) + (ac2.z + ac3.z);
    acc.w = (ac0.w + ac1.w) + (ac2.w + ac3.w);

    float dn = g_dinv[n];
    float4 b = ((const float4*)bias)[lane];
    float4 gm = ((const float4*)gamma)[lane];
    float4 bt = ((const float4*)beta)[lane];
    float4 mn = ((const float4*)mean)[lane];
    float4 vr = ((const float4*)var)[lane];
    float4 o;
    o.x = fmaxf(0.f, (dn * acc.x + b.x - mn.x) * rsqrtf(vr.x + BN_EPS) * gm.x + bt.x);
    o.y = fmaxf(0.f, (dn * acc.y + b.y - mn.y) * rsqrtf(vr.y + BN_EPS) * gm.y + bt.y);
    o.z = fmaxf(0.f, (dn * acc.z + b.z - mn.z) * rsqrtf(vr.z + BN_EPS) * gm.z + bt.z);
    o.w = fmaxf(0.f, (dn * acc.w + b.w - mn.w) * rsqrtf(vr.w + BN_EPS) * gm.w + bt.w);

    *(float4*)&os[wrp][lane * 4] = o;
    __syncwarp();

    // packed projection: lane = (col, k-half); 32 k2-steps of LDS.64 + FFMA2
    {
        int col = lane & 15;
        int kh = lane >> 4;                // 0 or 1
        const unsigned long long* osp =
            (const unsigned long long*)&os[wrp][kh * 64];          // 32 pairs
        const unsigned long long* wfp =
            (const unsigned long long*)&Wfp[kh * 32 * NC + col];   // stride NC pairs
        unsigned long long pacc = 0ULL;
#pragma unroll 8
        for (int k2 = 0; k2 < 32; k2++)
            ffma2(pacc, osp[k2], wfp[(size_t)k2 * NC]);
        float2 pr = unpack2(pacc);
        float s = pr.x + pr.y;
        s += __shfl_down_sync(0xffffffffu, s, 16);
        if (lane < 16)
            T[(size_t)n * NC + lane] = s * dn;
    }
}

// ---------------- aggregation L2: 4 threads/node; writes output; re-zeros cnt --
__global__ void agg16_k(const float* __restrict__ t, float* __restrict__ out) {
    int idx = blockIdx.x * blockDim.x + threadIdx.x;
    int n = idx >> 2;
    int q = idx & 3;
    if (n >= NN) return;
    if (q == 0) g_cnt[n] = 0;   // reset for next call (counts already consumed)
    const float4* t4 = (const float4*)t;

    float4 ac0 = t4[(size_t)n * 4 + q];  // self loop
    float4 ac1 = make_float4(0.f, 0.f, 0.f, 0.f);
    float4 ac2 = make_float4(0.f, 0.f, 0.f, 0.f);
    float4 ac3 = make_float4(0.f, 0.f, 0.f, 0.f);
    int jb = g_rowptr[n], je = g_rowptr[n + 1];
    int j = jb;
    for (; j + 4 <= je; j += 4) {
        float4 v0 = t4[(size_t)g_col[j]     * 4 + q];
        float4 v1 = t4[(size_t)g_col[j + 1] * 4 + q];
        float4 v2 = t4[(size_t)g_col[j + 2] * 4 + q];
        float4 v3 = t4[(size_t)g_col[j + 3] * 4 + q];
        ac0.x += v0.x; ac0.y += v0.y; ac0.z += v0.z; ac0.w += v0.w;
        ac1.x += v1.x; ac1.y += v1.y; ac1.z += v1.z; ac1.w += v1.w;
        ac2.x += v2.x; ac2.y += v2.y; ac2.z += v2.z; ac2.w += v2.w;
        ac3.x += v3.x; ac3.y += v3.y; ac3.z += v3.z; ac3.w += v3.w;
    }
    for (; j < je; j++) {
        float4 v = t4[(size_t)g_col[j] * 4 + q];
        ac0.x += v.x; ac0.y += v.y; ac0.z += v.z; ac0.w += v.w;
    }
    float4 acc;
    acc.x = (ac0.x + ac1.x) + (ac2.x + ac3.x);
    acc.y = (ac0.y + ac1.y) + (ac2.y + ac3.y);
    acc.z = (ac0.z + ac1.z) + (ac2.z + ac3.z);
    acc.w = (ac0.w + ac1.w) + (ac2.w + ac3.w);

    float dn = g_dinv[n];
    float4 b = ((const float4*)g_bf)[q];
    acc.x = dn * acc.x + b.x; acc.y = dn * acc.y + b.y;
    acc.z = dn * acc.z + b.z; acc.w = dn * acc.w + b.w;
    ((float4*)out)[(size_t)n * 4 + q] = acc;
}

// ---------------- launch (5 kernels) ----------------
extern "C" void kernel_launch(void* const* d_in, const int* in_sizes, int n_in,
                              void* d_out, int out_size) {
    const float* seq   = (const float*)d_in[0];
    const void*  ei    = d_in[1];
    const float* W1    = (const float*)d_in[2];
    const float* b1    = (const float*)d_in[3];
    const float* gamma = (const float*)d_in[4];
    const float* beta  = (const float*)d_in[5];
    const float* rmean = (const float*)d_in[6];
    const float* rvar  = (const float*)d_in[7];
    const float* W2    = (const float*)d_in[8];
    const float* b2    = (const float*)d_in[9];
    const float* Wc    = (const float*)d_in[10];
    const float* bc    = (const float*)d_in[11];
    float* out = (float*)d_out;

    float* gt = nullptr;
    cudaGetSymbolAddress((void**)&gt, g_t);

    int nsm = 148;
    cudaDeviceGetAttribute(&nsm, cudaDevAttrMultiProcessorCount, 0);
    if (nsm <= 0 || nsm > NTILES) nsm = 148;

    cudaFuncSetAttribute(gemm_k, cudaFuncAttributeMaxDynamicSharedMemorySize, GEMM_SMEM);

    // prep: Wf fuse + degree count (g_cnt zeroed by prior call / static init)
    prep_k<<<8 + NE / 4 / 256, 256>>>(W2, Wc, b2, bc, ei);
    scan_dinv_k<<<1, 1024>>>();

    // layer 1 GEMM + embedded CSR fill (fill overlaps async staging/compute)
    gemm_k<<<nsm, 512, GEMM_SMEM>>>(seq, W1, ei);
    agg128f_k<<<(NN * 32 + 255) / 256, 256>>>(gt, b1, gamma, beta, rmean, rvar);

    // layer 2 (pre-projected): out = dinv * agg(t-hat) + bf ; also re-zero cnt
    agg16_k<<<(NN * 4 + 255) / 256, 256>>>(gt, out);
}